// round 14
// baseline (speedup 1.0000x reference)
#include <cuda_runtime.h>

// ---------------------------------------------------------------------------
// PhotonicLayer via TF32 tensor cores (mma.sync.m16n8k8), fragment-packed.
// Real GEMM: X=[xr|xi] (Bx128), W=[[Ur,-Ui],[Ui,Ur]] (128x128), out'=X@W^T.
// K1: barrier-free streaming build — thread t owns column t; ping-pong
//     buffers (no aliasing), untouched rows synthesized as identity.
// K2: 512-thread tensor-core GEMM (32 warps/SM), fragment-packed A in smem,
//     register epilogue with in-warp re/im pairing, direct float2 stores.
// ---------------------------------------------------------------------------

#define SIZE 64
#define NPH 2016
#define LOSS_AMP 0.9942600740f      // 10^(-0.05/20)
#define KERR 2.6e-17f               // NONLINEAR_COEFF * 1000

// W in fragment order: flat idx = (((n8t*16 + ks)*32 + lane)*2 + q)
__device__ unsigned g_Wfrag[16 * 16 * 32 * 2];   // 64 KB

// ---------------------------- build kernel --------------------------------
__global__ __launch_bounds__(64)
void build_u_kernel(const float* __restrict__ phases, int nph) {
    extern __shared__ char bsm[];
    float2 (*Sa)[SIZE] = (float2(*)[SIZE])bsm;            // 32 KB
    float2 (*Sb)[SIZE] = (float2(*)[SIZE])(bsm + 32768);  // 32 KB
    float2* ang = (float2*)(bsm + 65536);                 // NPH float2

    const int t = threadIdx.x;       // column 0..63
    const int pmax = (nph > 0) ? (nph - 1) : 0;

    for (int k = t; k < NPH; k += 64) {
        const int kk = (k < pmax) ? k : pmax;
        float sv, cv;
        sincosf(phases[kk], &sv, &cv);
        ang[k] = make_float2(LOSS_AMP * cv, LOSS_AMP * sv);
    }
    // only state row 0 is ever loaded before being written: init it.
    Sa[0][t] = make_float2(t == 0 ? 1.0f : 0.0f, 0.0f);
    __syncthreads();

    // Layer i reads rows 0..i-1 from src (written by layer i-1) and
    // synthesizes row i as identity; writes rows 0..i to dst. Each thread
    // touches only column t -> no barriers, no aliasing (src != dst).
    int kk = 0;
    for (int i = 1; i < SIZE; ++i) {
        float2 (*src)[SIZE] = (i & 1) ? Sa : Sb;
        float2 (*dst)[SIZE] = (i & 1) ? Sb : Sa;
        float ar = src[0][t].x, ai = src[0][t].y;
        #pragma unroll 4
        for (int j = 0; j < i; ++j, ++kk) {
            const float2 a2 = ang[kk];
            float br, bi;
            if (j + 1 < i) {
                const float2 b = src[j + 1][t];
                br = b.x; bi = b.y;
            } else {                       // row i still identity
                br = (t == i) ? 1.0f : 0.0f; bi = 0.0f;
            }
            const float cc = a2.x, ss = a2.y;
            dst[j][t] = make_float2(fmaf(cc, ar, -(ss * bi)),
                                    fmaf(cc, ai,   ss * br));
            const float nbr = fmaf(cc, br, -(ss * ai));
            const float nbi = fmaf(cc, bi,   ss * ar);
            ar = nbr; ai = nbi;
        }
        dst[i][t] = make_float2(ar, ai);
    }
    __syncthreads();
    // final state: dst of layer 63 (odd) = Sb

    // emit W[n'][k'] tf32-rounded in mma B-fragment order:
    //   n'<64: [ Ur | -Ui ] ; n'>=64: [ Ui | Ur ]
    for (int p = t; p < 128 * 128; p += 64) {
        const int n = p >> 7, k = p & 127;
        const float2 u = Sb[n & 63][k & 63];
        float v;
        if (n < 64) v = (k < 64) ? u.x : -u.y;
        else        v = (k < 64) ? u.y :  u.x;
        unsigned tv;
        asm("cvt.rna.tf32.f32 %0, %1;" : "=r"(tv) : "f"(v));
        const int n8t = n >> 3, g = n & 7;
        const int ks = k >> 3, tt = k & 3, q = (k >> 2) & 1;
        g_Wfrag[(((n8t * 16 + ks) * 32 + g * 4 + tt) << 1) + q] = tv;
    }
}

// ----------------------------- GEMM kernel --------------------------------
// 512 threads (16 warps: warpM 0..3 x warpN 0..3). Tile: 128 b x 128 n'.
// Each warp: 2 m16-tiles x 4 n8-tiles {2w, 2w+1, 2w+8, 2w+9} (re/im pairing).
__global__ __launch_bounds__(512, 2)
void photonic_mma_kernel(const float* __restrict__ xr_g,
                         const float* __restrict__ xi_g,
                         float* __restrict__ out,
                         long long xsz, long long out_elems, int B) {
    extern __shared__ char smem[];
    unsigned* sxA = (unsigned*)smem;          // packed A: 64 KB

    const int tid  = threadIdx.x;
    const int lane = tid & 31;
    const int warp = tid >> 5;                // 0..15
    const int g = lane >> 2;                  // groupID 0..7
    const int t = lane & 3;                   // thread-in-group 0..3
    const int warpM = warp >> 2;              // 0..3
    const int warpN = warp & 3;               // 0..3

    const long long b0 = (long long)blockIdx.x * 128;
    if (b0 >= B) return;
    const long long base = b0 * SIZE;
    const long long xmax = xsz - 1;

    // ---- stage X = [xr | xi], tf32-rounded, in A-fragment order ----
    for (int p = tid; p < 128 * 64; p += 512) {
        const int bb = p >> 6, k = p & 63;
        long long gi = base + p;
        if (gi > xmax) gi = xmax;
        const float vr = xr_g[gi];
        const float vi = xi_g[gi];
        unsigned r_, i_;
        asm("cvt.rna.tf32.f32 %0, %1;" : "=r"(r_) : "f"(vr));
        asm("cvt.rna.tf32.f32 %0, %1;" : "=r"(i_) : "f"(vi));
        const int m16t = bb >> 4, gg = bb & 7, half = (bb >> 3) & 1;
        const int tt = k & 3, q = (k >> 2) & 1;
        const int bse = (m16t * 16) * 128 + (gg * 4 + tt) * 4 + half + 2 * q;
        sxA[bse + ((k >> 3)) * 128]     = r_;   // re: ks = k>>3
        sxA[bse + ((k >> 3) + 8) * 128] = i_;   // im: ks = k>>3 + 8
    }
    __syncthreads();

    // ---- accumulators: c[mt][cidx][4]; cidx 0,1 = re tiles, 2,3 = im ----
    float c[2][4][4];
    #pragma unroll
    for (int mt = 0; mt < 2; ++mt)
        #pragma unroll
        for (int nt = 0; nt < 4; ++nt)
            #pragma unroll
            for (int q2 = 0; q2 < 4; ++q2) c[mt][nt][q2] = 0.0f;

    // n8-tile ids for this warp: {2w, 2w+1, 2w+8, 2w+9}
    int n8tab[4];
    n8tab[0] = warpN * 2;     n8tab[1] = warpN * 2 + 1;
    n8tab[2] = warpN * 2 + 8; n8tab[3] = warpN * 2 + 9;

    #pragma unroll 4
    for (int ks = 0; ks < 16; ++ks) {
        uint4 a[2];
        #pragma unroll
        for (int mt = 0; mt < 2; ++mt)
            a[mt] = *(const uint4*)&sxA[(((warpM * 2 + mt) * 16 + ks) * 32
                                         + lane) * 4];
        uint2 bf[4];
        #pragma unroll
        for (int nt = 0; nt < 4; ++nt)
            bf[nt] = __ldg((const uint2*)&g_Wfrag[
                (((n8tab[nt] * 16 + ks) * 32 + lane) << 1)]);
        #pragma unroll
        for (int mt = 0; mt < 2; ++mt)
            #pragma unroll
            for (int nt = 0; nt < 4; ++nt)
                asm volatile(
                    "mma.sync.aligned.m16n8k8.row.col.f32.tf32.tf32.f32 "
                    "{%0,%1,%2,%3}, {%4,%5,%6,%7}, {%8,%9}, {%0,%1,%2,%3};"
                    : "+f"(c[mt][nt][0]), "+f"(c[mt][nt][1]),
                      "+f"(c[mt][nt][2]), "+f"(c[mt][nt][3])
                    : "r"(a[mt].x), "r"(a[mt].y), "r"(a[mt].z), "r"(a[mt].w),
                      "r"(bf[nt].x), "r"(bf[nt].y));
    }

    // ---- register epilogue: pair re (cidx) with im (cidx+2), Kerr, store ----
    #pragma unroll
    for (int mt = 0; mt < 2; ++mt) {
        const int row0 = (warpM * 2 + mt) * 16 + g;
        #pragma unroll
        for (int ci = 0; ci < 2; ++ci) {
            const int n = (warpN * 2 + ci) * 8 + 2 * t;
            #pragma unroll
            for (int h = 0; h < 2; ++h) {
                const int row = row0 + 8 * h;
                const float re0 = c[mt][ci][2 * h];
                const float re1 = c[mt][ci][2 * h + 1];
                const float im0 = c[mt][ci + 2][2 * h];
                const float im1 = c[mt][ci + 2][2 * h + 1];
                const float ph0 = KERR * fmaf(re0, re0, im0 * im0);
                const float ph1 = KERR * fmaf(re1, re1, im1 * im1);
                const long long o = base + (long long)row * 64 + n;
                if (o + 2 <= out_elems)
                    *(float2*)&out[o] = make_float2(fmaf(-im0, ph0, re0),
                                                    fmaf(-im1, ph1, re1));
            }
        }
    }
}

// ------------------------------- launch ------------------------------------
extern "C" void kernel_launch(void* const* d_in, const int* in_sizes, int n_in,
                              void* d_out, int out_size) {
    if (n_in < 3) return;

    // phases = the input with the smallest element count (2016 vs B*64)
    int ph_idx = 0;
    for (int i = 1; i < 3; ++i)
        if (in_sizes[i] < in_sizes[ph_idx]) ph_idx = i;

    const float* xr = nullptr;
    const float* xi = nullptr;
    long long xsz = 0;
    for (int i = 0; i < 3; ++i) {
        if (i == ph_idx) continue;
        if (!xr) { xr = (const float*)d_in[i]; xsz = in_sizes[i]; }
        else     { xi = (const float*)d_in[i]; }
    }
    const float* phases = (const float*)d_in[ph_idx];
    const int nph = in_sizes[ph_idx];

    const int B = (int)(xsz / SIZE);
    const int nblocks = (B + 127) / 128;

    const int build_smem = 65536 + NPH * 8;   // 81,664 B
    cudaFuncSetAttribute(build_u_kernel,
                         cudaFuncAttributeMaxDynamicSharedMemorySize,
                         build_smem);
    cudaFuncSetAttribute(photonic_mma_kernel,
                         cudaFuncAttributeMaxDynamicSharedMemorySize,
                         65536);

    build_u_kernel<<<1, 64, build_smem>>>(phases, nph);
    photonic_mma_kernel<<<nblocks, 512, 65536>>>(
        xr, xi, (float*)d_out, xsz, (long long)out_size, B);
}

// round 16
// speedup vs baseline: 1.8384x; 1.8384x over previous
#include <cuda_runtime.h>

// ---------------------------------------------------------------------------
// PhotonicLayer via TF32 tensor cores (mma.sync.m16n8k8), fragment-packed.
// Real GEMM: X=[xr|xi] (Bx128), W=[[Ur,-Ui],[Ui,Ur]] (128x128), out'=X@W^T.
// A (X) staged in smem in fragment order -> LDS.128 per fragment.
// B (W) prepacked by build kernel in fragment order -> coalesced LDG.64.
// Mainloop FULLY unrolled (compile-time operand offsets -> deep software
// pipelining by ptxas). Register epilogue with in-warp re/im pairing.
// ---------------------------------------------------------------------------

#define SIZE 64
#define NPH 2016
#define LOSS_AMP 0.9942600740f      // 10^(-0.05/20)
#define KERR 2.6e-17f               // NONLINEAR_COEFF * 1000
#define BT 672                      // build threads = 21 warps (widest wave)

// W in fragment order: flat idx = (((n8t*16 + ks)*32 + lane)*2 + q)
__device__ unsigned g_Wfrag[16 * 16 * 32 * 2];   // 64 KB

// ---------------------------- build kernel --------------------------------
// Wavefront schedule: rotation (i,j) at T = 2i+j; same-T rotations touch
// disjoint row pairs -> in-place, one barrier per wavefront (187 waves =
// the DAG critical path).
__global__ __launch_bounds__(BT)
void build_u_kernel(const float* __restrict__ phases, int nph) {
    __shared__ float2 S[SIZE][SIZE];    // [row][col] = U
    __shared__ float cs[NPH];
    __shared__ float sn[NPH];

    const int tid  = threadIdx.x;
    const int lane = tid & 31;
    const int warp = tid >> 5;
    const int pmax = (nph > 0) ? (nph - 1) : 0;

    for (int k = tid; k < NPH; k += BT) {
        const int kk = (k < pmax) ? k : pmax;
        float sv, cv;
        sincosf(phases[kk], &sv, &cv);
        cs[k] = LOSS_AMP * cv;
        sn[k] = LOSS_AMP * sv;
    }
    for (int p = tid; p < SIZE * SIZE; p += BT) {
        const int r = p >> 6, c = p & 63;
        S[r][c] = make_float2(r == c ? 1.0f : 0.0f, 0.0f);
    }
    __syncthreads();

    for (int w = 2; w <= 188; ++w) {
        int i_min = (w + 3) / 3; if (i_min < 1) i_min = 1;
        int i_max = w >> 1;      if (i_max > 63) i_max = 63;
        const int cnt = i_max - i_min + 1;   // <= 21

        if (warp < cnt) {
            const int i = i_min + warp;
            const int j = w - 2 * i;
            const int k = ((i * (i - 1)) >> 1) + j;
            const float cc = cs[k], ss = sn[k];
            #pragma unroll
            for (int h = 0; h < 2; ++h) {
                const int c = lane + 32 * h;
                const float2 a = S[j][c];
                const float2 b = S[j + 1][c];
                S[j][c]     = make_float2(fmaf(cc, a.x, -(ss * b.y)),
                                          fmaf(cc, a.y,   ss * b.x));
                S[j + 1][c] = make_float2(fmaf(cc, b.x, -(ss * a.y)),
                                          fmaf(cc, b.y,   ss * a.x));
            }
        }
        __syncthreads();
    }

    // emit W[n'][k'] tf32-rounded in mma B-fragment order:
    //   n'<64: [ Ur | -Ui ] ; n'>=64: [ Ui | Ur ]
    for (int p = tid; p < 128 * 128; p += BT) {
        const int n = p >> 7, k = p & 127;
        const float2 u = S[n & 63][k & 63];
        float v;
        if (n < 64) v = (k < 64) ? u.x : -u.y;
        else        v = (k < 64) ? u.y :  u.x;
        unsigned tv;
        asm("cvt.rna.tf32.f32 %0, %1;" : "=r"(tv) : "f"(v));
        const int n8t = n >> 3, g = n & 7;
        const int ks = k >> 3, t = k & 3, q = (k >> 2) & 1;
        g_Wfrag[(((n8t * 16 + ks) * 32 + g * 4 + t) << 1) + q] = tv;
    }
}

// ----------------------------- GEMM kernel --------------------------------
// 256 threads (8 warps: warpM 0..1 x warpN 0..3). Tile: 128 b x 128 n', K=128.
// warpN owns n8-tiles {2w, 2w+1, 2w+8, 2w+9} -> re/im pairing in registers.
__global__ __launch_bounds__(256, 2)
void photonic_mma_kernel(const float* __restrict__ xr_g,
                         const float* __restrict__ xi_g,
                         float* __restrict__ out,
                         long long xsz, long long out_elems, int B) {
    extern __shared__ char smem[];
    unsigned* sxA = (unsigned*)smem;          // packed A: 64 KB

    const int tid  = threadIdx.x;
    const int lane = tid & 31;
    const int warp = tid >> 5;
    const int g = lane >> 2;                  // groupID 0..7
    const int t = lane & 3;                   // thread-in-group 0..3
    const int warpM = warp >> 2;              // 0..1
    const int warpN = warp & 3;               // 0..3

    const long long b0 = (long long)blockIdx.x * 128;
    if (b0 >= B) return;
    const long long base = b0 * SIZE;
    const long long xmax = xsz - 1;

    // ---- stage X = [xr | xi], tf32-rounded, in A-fragment order ----
    #pragma unroll 8
    for (int p = tid; p < 128 * 64; p += 256) {
        const int bb = p >> 6, k = p & 63;
        long long gi = base + p;
        if (gi > xmax) gi = xmax;
        const float vr = xr_g[gi];
        const float vi = xi_g[gi];
        unsigned r_, i_;
        asm("cvt.rna.tf32.f32 %0, %1;" : "=r"(r_) : "f"(vr));
        asm("cvt.rna.tf32.f32 %0, %1;" : "=r"(i_) : "f"(vi));
        const int m16t = bb >> 4, gg = bb & 7, half = (bb >> 3) & 1;
        const int tt = k & 3, q = (k >> 2) & 1;
        const int bse = (m16t * 16) * 128 + (gg * 4 + tt) * 4 + half + 2 * q;
        sxA[bse + ((k >> 3)) * 128]     = r_;   // re: ks = k>>3
        sxA[bse + ((k >> 3) + 8) * 128] = i_;   // im: ks = k>>3 + 8
    }
    __syncthreads();

    // ---- accumulators: c[mt][cidx][4]; cidx 0,1 = re tiles, 2,3 = im ----
    float c[4][4][4];
    #pragma unroll
    for (int mt = 0; mt < 4; ++mt)
        #pragma unroll
        for (int nt = 0; nt < 4; ++nt)
            #pragma unroll
            for (int q2 = 0; q2 < 4; ++q2) c[mt][nt][q2] = 0.0f;

    // per-warp bases: all mainloop offsets become compile-time immediates
    const unsigned* sA = &sxA[((warpM * 4) * 16) * 128 + lane * 4];
    const unsigned* wp0 = &g_Wfrag[(((warpN * 2    ) * 16) * 32 + lane) << 1];
    const unsigned* wp1 = &g_Wfrag[(((warpN * 2 + 1) * 16) * 32 + lane) << 1];
    const unsigned* wp2 = &g_Wfrag[(((warpN * 2 + 8) * 16) * 32 + lane) << 1];
    const unsigned* wp3 = &g_Wfrag[(((warpN * 2 + 9) * 16) * 32 + lane) << 1];

    #pragma unroll
    for (int ks = 0; ks < 16; ++ks) {
        uint4 a[4];
        #pragma unroll
        for (int mt = 0; mt < 4; ++mt)
            a[mt] = *(const uint4*)&sA[(mt * 16 + ks) * 128];
        uint2 bf[4];
        bf[0] = __ldg((const uint2*)&wp0[ks * 64]);
        bf[1] = __ldg((const uint2*)&wp1[ks * 64]);
        bf[2] = __ldg((const uint2*)&wp2[ks * 64]);
        bf[3] = __ldg((const uint2*)&wp3[ks * 64]);
        #pragma unroll
        for (int mt = 0; mt < 4; ++mt)
            #pragma unroll
            for (int nt = 0; nt < 4; ++nt)
                asm volatile(
                    "mma.sync.aligned.m16n8k8.row.col.f32.tf32.tf32.f32 "
                    "{%0,%1,%2,%3}, {%4,%5,%6,%7}, {%8,%9}, {%0,%1,%2,%3};"
                    : "+f"(c[mt][nt][0]), "+f"(c[mt][nt][1]),
                      "+f"(c[mt][nt][2]), "+f"(c[mt][nt][3])
                    : "r"(a[mt].x), "r"(a[mt].y), "r"(a[mt].z), "r"(a[mt].w),
                      "r"(bf[nt].x), "r"(bf[nt].y));
    }

    // ---- register epilogue: pair re (cidx) with im (cidx+2), Kerr, store ----
    #pragma unroll
    for (int mt = 0; mt < 4; ++mt) {
        const int row0 = warpM * 64 + mt * 16 + g;
        #pragma unroll
        for (int ci = 0; ci < 2; ++ci) {
            const int n = (warpN * 2 + ci) * 8 + 2 * t;
            #pragma unroll
            for (int h = 0; h < 2; ++h) {
                const int row = row0 + 8 * h;
                const float re0 = c[mt][ci][2 * h];
                const float re1 = c[mt][ci][2 * h + 1];
                const float im0 = c[mt][ci + 2][2 * h];
                const float im1 = c[mt][ci + 2][2 * h + 1];
                const float ph0 = KERR * fmaf(re0, re0, im0 * im0);
                const float ph1 = KERR * fmaf(re1, re1, im1 * im1);
                const long long o = base + (long long)row * 64 + n;
                if (o + 2 <= out_elems)
                    *(float2*)&out[o] = make_float2(fmaf(-im0, ph0, re0),
                                                    fmaf(-im1, ph1, re1));
            }
        }
    }
}

// ------------------------------- launch ------------------------------------
extern "C" void kernel_launch(void* const* d_in, const int* in_sizes, int n_in,
                              void* d_out, int out_size) {
    if (n_in < 3) return;

    // phases = the input with the smallest element count (2016 vs B*64)
    int ph_idx = 0;
    for (int i = 1; i < 3; ++i)
        if (in_sizes[i] < in_sizes[ph_idx]) ph_idx = i;

    const float* xr = nullptr;
    const float* xi = nullptr;
    long long xsz = 0;
    for (int i = 0; i < 3; ++i) {
        if (i == ph_idx) continue;
        if (!xr) { xr = (const float*)d_in[i]; xsz = in_sizes[i]; }
        else     { xi = (const float*)d_in[i]; }
    }
    const float* phases = (const float*)d_in[ph_idx];
    const int nph = in_sizes[ph_idx];

    const int B = (int)(xsz / SIZE);
    const int nblocks = (B + 127) / 128;

    cudaFuncSetAttribute(photonic_mma_kernel,
                         cudaFuncAttributeMaxDynamicSharedMemorySize,
                         65536);

    build_u_kernel<<<1, BT>>>(phases, nph);
    photonic_mma_kernel<<<nblocks, 256, 65536>>>(
        xr, xi, (float*)d_out, xsz, (long long)out_size, B);
}